// round 16
// baseline (speedup 1.0000x reference)
#include <cuda_runtime.h>

// Problem constants (z: [8192, 20, 256] f32, labels: [8192] i32, K=10)
#define NUM_LABELS 10
#define B_ROWS     8192
#define CH         5120          // C*H = 20*256
#define EPS        1e-8f

#define TPB            128
#define COLS_PER_CTA   512       // TPB * 4 (float4 per thread)
#define ROWS_PER_CHUNK 128
#define COL_BLOCKS     (CH / COLS_PER_CTA)          // 10
#define ROW_CHUNKS     (B_ROWS / ROWS_PER_CHUNK)    // 64

// Megakernel v2: prep CTAs + accum CTAs (accum CTAs also do the finalize).
#define PREP_CTAS   8                               // bids 0..7
#define ACCUM_CTAS  (COL_BLOCKS * ROW_CHUNKS)       // 640, bids 8..647
#define GRID_CTAS   (PREP_CTAS + ACCUM_CTAS)        // 648  (<= 148*8 slots)
#define FIN_CTAS    400                             // first 400 accum CTAs finalize
#define EIGHTH4     (B_ROWS / PREP_CTAS / 4)        // 256 int4 per prep CTA

// Scratch (allocation-free: __device__ globals).
// INVARIANT at kernel entry (module load + self-cleaning each replay):
//   g_sum/g_sum2 all-zero, counters 0, flags 0.
__device__ __align__(16)  float g_sum [NUM_LABELS * CH];
__device__ __align__(16)  float g_sum2[NUM_LABELS * CH];
__device__ __align__(128) int   g_rl[B_ROWS];   // (row<<4)|label, globally grouped
__device__ int g_counts[NUM_LABELS];
__device__ int g_c1, g_c2, g_p2;                // completion counters (self-reset)
__device__ volatile int g_f1, g_f2;             // phase flags (self-reset)

// ---------------------------------------------------------------------------
// Phase 1 (noinline): global label grouping, one eighth per CTA.
// ---------------------------------------------------------------------------
__device__ __noinline__ void prep_phase(int c, const int* __restrict__ labels,
                                        float* __restrict__ out) {
    __shared__ int bins[PREP_CTAS][NUM_LABELS];  // one row per eighth
    __shared__ int cursor[NUM_LABELS];
    const int tid  = threadIdx.x;
    const int wid  = tid >> 5;                   // 0..3
    const int lane = tid & 31;
    const int4* __restrict__ lab4 = (const int4*)labels;

    // Stash my 2 scatter int4s early (latency overlaps hist phase)
    const int my_i4 = c * EIGHTH4 + tid * 2;
    const int4 s0 = lab4[my_i4];
    const int4 s1 = lab4[my_i4 + 1];

    if (c == 0 && tid == 0) out[0] = 0.0f;
    if (tid < PREP_CTAS * NUM_LABELS) ((int*)bins)[tid] = 0;
    __syncthreads();

    // Warp w histograms eighths 2w (it 0..7) and 2w+1 (it 8..15)
    #pragma unroll
    for (int it = 0; it < 16; it++) {
        int4 v = lab4[wid * 512 + it * 32 + lane];
        int row = wid * 2 + (it >= 8);
        atomicAdd(&bins[row][v.x], 1);
        atomicAdd(&bins[row][v.y], 1);
        atomicAdd(&bins[row][v.z], 1);
        atomicAdd(&bins[row][v.w], 1);
    }
    __syncthreads();

    // Warp 0, lanes 0..9: totals + shfl exclusive scan + my-eighth base
    if (wid == 0) {
        const int k = lane;
        int tot = 0, mybase = 0;
        if (k < NUM_LABELS) {
            #pragma unroll
            for (int e = 0; e < PREP_CTAS; e++) tot += bins[e][k];
            for (int e = 0; e < c; e++) mybase += bins[e][k];
        }
        int scan = (k < NUM_LABELS) ? tot : 0;
        #pragma unroll
        for (int o = 1; o < 16; o <<= 1) {
            int t = __shfl_up_sync(0xffffffffu, scan, o);
            if (lane >= o) scan += t;
        }
        if (k < NUM_LABELS) {
            cursor[k] = (scan - tot) + mybase;
            if (c == 0) g_counts[k] = tot;
        }
    }
    __syncthreads();

    // Scatter my eighth from registers (warp-aggregated smem cursors)
    #pragma unroll
    for (int s = 0; s < 2; s++) {
        const int4 v = s ? s1 : s0;
        const int b0 = (my_i4 + s) * 4;
        #pragma unroll
        for (int j = 0; j < 4; j++) {
            int lab = (j == 0) ? v.x : (j == 1) ? v.y : (j == 2) ? v.z : v.w;
            unsigned mask = __match_any_sync(0xffffffffu, lab);
            int leader = __ffs(mask) - 1;
            int rank   = __popc(mask & ((1u << lane) - 1u));
            int base = 0;
            if (lane == leader) base = atomicAdd(&cursor[lab], __popc(mask));
            base = __shfl_sync(0xffffffffu, base, leader);
            g_rl[base + rank] = ((b0 + j) << 4) | lab;
        }
    }

    __threadfence();                 // release g_rl / g_counts / out
    __syncthreads();
    if (tid == 0) {
        if (atomicAdd(&g_c1, 1) == PREP_CTAS - 1) {
            g_c1 = 0;
            g_f1 = 1;                // open accum phase
        }
    }
}

// ---------------------------------------------------------------------------
// Phase 3 (noinline): finalize 128 cells for CTA b2 (0..399).
// sse(k,j) = q - 2*m'*s + n*m'^2, m' = s/n - EPS. Zero-restores cells.
// ---------------------------------------------------------------------------
__device__ __noinline__ void finalize_phase(int b2, float* __restrict__ out) {
    __shared__ float sh[4];
    const int tid  = threadIdx.x;
    const int lane = tid & 31;
    const int k = b2 / (FIN_CTAS / NUM_LABELS);          // 40 CTAs per label
    const int j = (b2 % (FIN_CTAS / NUM_LABELS)) * TPB + tid;

    const int idx = k * CH + j;
    float n = (float)g_counts[k];
    float s = g_sum[idx];
    float q = g_sum2[idx];
    g_sum[idx]  = 0.0f;              // restore all-zero invariant
    g_sum2[idx] = 0.0f;

    float acc = 0.0f;
    if (n > 0.0f) {
        float mp = s / n - EPS;
        float e  = q - 2.0f * mp * s + n * mp * mp;
        acc = e / (n * (float)CH);
    }
    #pragma unroll
    for (int o = 16; o > 0; o >>= 1)
        acc += __shfl_down_sync(0xffffffffu, acc, o);
    if (lane == 0) sh[tid >> 5] = acc;
    __syncthreads();
    if (tid == 0) atomicAdd(out, sh[0] + sh[1] + sh[2] + sh[3]);
}

__device__ __forceinline__ void flush_acc(int lab, int colBase,
                                          float4& a, float4& a2) {
    int base = lab * CH + colBase;
    atomicAdd(&g_sum [base + 0], a.x);
    atomicAdd(&g_sum [base + 1], a.y);
    atomicAdd(&g_sum [base + 2], a.z);
    atomicAdd(&g_sum [base + 3], a.w);
    atomicAdd(&g_sum2[base + 0], a2.x);
    atomicAdd(&g_sum2[base + 1], a2.y);
    atomicAdd(&g_sum2[base + 2], a2.z);
    atomicAdd(&g_sum2[base + 3], a2.w);
    a  = make_float4(0.f, 0.f, 0.f, 0.f);
    a2 = make_float4(0.f, 0.f, 0.f, 0.f);
}

// ---------------------------------------------------------------------------
// Megakernel v2: 648 CTAs, all co-resident (<=64 regs, 8/SM slots).
// bids 0..7 prep; bids 8..647 accum, then the first 400 of them finalize.
// ---------------------------------------------------------------------------
__global__ __launch_bounds__(TPB, 8) void mega_kernel(const float* __restrict__ z,
                                                      const int* __restrict__ labels,
                                                      float* __restrict__ out) {
    const int tid = threadIdx.x;
    const int bid = blockIdx.x;

    if (bid < PREP_CTAS) {
        prep_phase(bid, labels, out);
        return;
    }

    // ===================== accum (bids 8..647) ==============================
    __shared__ int s_rl[ROWS_PER_CHUNK];
    const int b  = bid - PREP_CTAS;
    const int cb = b % COL_BLOCKS;   // column block 0..9
    const int rc = b / COL_BLOCKS;   // row chunk   0..63

    if (tid == 0) { while (g_f1 == 0) __nanosleep(256); }
    __syncthreads();
    __threadfence();                 // acquire prep's writes

    s_rl[tid] = g_rl[rc * ROWS_PER_CHUNK + tid];
    __syncthreads();

    const float4* __restrict__ z4 = (const float4*)z;
    const int col4    = cb * (COLS_PER_CTA / 4) + tid;
    const int colBase = cb * COLS_PER_CTA + tid * 4;

    float4 a  = make_float4(0.f, 0.f, 0.f, 0.f);
    float4 a2 = make_float4(0.f, 0.f, 0.f, 0.f);
    int cur = s_rl[0] & 15;

    for (int i = 0; i < ROWS_PER_CHUNK; i += 8) {
        int    rl[8];
        float4 v[8];
        #pragma unroll
        for (int u = 0; u < 8; u++) rl[u] = s_rl[i + u];
        #pragma unroll
        for (int u = 0; u < 8; u++) v[u] = z4[(rl[u] >> 4) * (CH / 4) + col4];

        #pragma unroll
        for (int u = 0; u < 8; u++) {
            int lab = rl[u] & 15;
            if (lab != cur) { flush_acc(cur, colBase, a, a2); cur = lab; }
            a.x += v[u].x; a.y += v[u].y; a.z += v[u].z; a.w += v[u].w;
            a2.x = fmaf(v[u].x, v[u].x, a2.x);
            a2.y = fmaf(v[u].y, v[u].y, a2.y);
            a2.z = fmaf(v[u].z, v[u].z, a2.z);
            a2.w = fmaf(v[u].w, v[u].w, a2.w);
        }
    }
    flush_acc(cur, colBase, a, a2);

    // ---- phase barrier: all accum atomics visible, then finalize ----
    __threadfence();
    __syncthreads();
    if (tid == 0) {
        if (atomicAdd(&g_c2, 1) == ACCUM_CTAS - 1) {
            g_c2 = 0;
            __threadfence();
            g_f2 = 1;                // open finalize phase
        }
        while (g_f2 == 0) __nanosleep(256);   // short: only finish-spread wait
    }
    __syncthreads();
    __threadfence();                 // acquire all CTAs' atomics

    if (b < FIN_CTAS) finalize_phase(b, out);

    __syncthreads();
    if (tid == 0) {
        if (atomicAdd(&g_p2, 1) == ACCUM_CTAS - 1) {
            g_p2 = 0;                // everyone is past the flag spins
            g_f1 = 0;                // reset for next replay
            g_f2 = 0;
        }
    }
}

// ---------------------------------------------------------------------------
extern "C" void kernel_launch(void* const* d_in, const int* in_sizes, int n_in,
                              void* d_out, int out_size) {
    const float* z      = (const float*)d_in[0];
    const int*   labels = (const int*)d_in[1];
    (void)in_sizes; (void)n_in; (void)out_size;

    mega_kernel<<<GRID_CTAS, TPB>>>(z, labels, (float*)d_out);
}

// round 17
// speedup vs baseline: 1.1558x; 1.1558x over previous
#include <cuda_runtime.h>

// Problem constants (z: [8192, 20, 256] f32, labels: [8192] i32, K=10)
#define NUM_LABELS 10
#define B_ROWS     8192
#define CH         5120          // C*H = 20*256
#define EPS        1e-8f

#define TPB            128
#define COLS_PER_CTA   512       // TPB * 4 (float4 per thread)
#define ROWS_PER_CHUNK 128
#define COL_BLOCKS     (CH / COLS_PER_CTA)          // 10
#define ROW_CHUNKS     (B_ROWS / ROWS_PER_CHUNK)    // 64

// Megakernel: prep CTAs + accum CTAs (accum CTAs also do the finalize).
#define PREP_CTAS   8                               // bids 0..7
#define ACCUM_CTAS  (COL_BLOCKS * ROW_CHUNKS)       // 640, bids 8..647
#define GRID_CTAS   (PREP_CTAS + ACCUM_CTAS)        // 648
#define FIN_CTAS    400                             // first 400 accum CTAs finalize
#define EIGHTH4     (B_ROWS / PREP_CTAS / 4)        // 256 int4 per prep CTA

// Residency: __launch_bounds__(128, 5) -> reg cap ~102 (no spills; accum's
// natural allocation is ~60-80 with phase plumbing), and 148*5 = 740 resident
// CTA slots >= 648, so ALL CTAs are co-resident in wave 1 -> spins can't deadlock.
#define MIN_CTAS_PER_SM 5

// Scratch (allocation-free: __device__ globals).
// INVARIANT at kernel entry (module load + self-cleaning each replay):
//   g_sum/g_sum2 all-zero, counters 0, flags 0.
__device__ __align__(16)  float g_sum [NUM_LABELS * CH];
__device__ __align__(16)  float g_sum2[NUM_LABELS * CH];
__device__ __align__(128) int   g_rl[B_ROWS];   // (row<<4)|label, globally grouped
__device__ int g_counts[NUM_LABELS];
__device__ int g_c1, g_c2, g_p2;                // completion counters (self-reset)
__device__ volatile int g_f1, g_f2;             // phase flags (self-reset)

// ---------------------------------------------------------------------------
// Phase 1 (noinline): global label grouping, one eighth per CTA.
// ---------------------------------------------------------------------------
__device__ __noinline__ void prep_phase(int c, const int* __restrict__ labels,
                                        float* __restrict__ out) {
    __shared__ int bins[PREP_CTAS][NUM_LABELS];  // one row per eighth
    __shared__ int cursor[NUM_LABELS];
    const int tid  = threadIdx.x;
    const int wid  = tid >> 5;                   // 0..3
    const int lane = tid & 31;
    const int4* __restrict__ lab4 = (const int4*)labels;

    // Stash my 2 scatter int4s early (latency overlaps hist phase)
    const int my_i4 = c * EIGHTH4 + tid * 2;
    const int4 s0 = lab4[my_i4];
    const int4 s1 = lab4[my_i4 + 1];

    if (c == 0 && tid == 0) out[0] = 0.0f;
    if (tid < PREP_CTAS * NUM_LABELS) ((int*)bins)[tid] = 0;
    __syncthreads();

    // Warp w histograms eighths 2w (it 0..7) and 2w+1 (it 8..15)
    #pragma unroll
    for (int it = 0; it < 16; it++) {
        int4 v = lab4[wid * 512 + it * 32 + lane];
        int row = wid * 2 + (it >= 8);
        atomicAdd(&bins[row][v.x], 1);
        atomicAdd(&bins[row][v.y], 1);
        atomicAdd(&bins[row][v.z], 1);
        atomicAdd(&bins[row][v.w], 1);
    }
    __syncthreads();

    // Warp 0, lanes 0..9: totals + shfl exclusive scan + my-eighth base
    if (wid == 0) {
        const int k = lane;
        int tot = 0, mybase = 0;
        if (k < NUM_LABELS) {
            #pragma unroll
            for (int e = 0; e < PREP_CTAS; e++) tot += bins[e][k];
            for (int e = 0; e < c; e++) mybase += bins[e][k];
        }
        int scan = (k < NUM_LABELS) ? tot : 0;
        #pragma unroll
        for (int o = 1; o < 16; o <<= 1) {
            int t = __shfl_up_sync(0xffffffffu, scan, o);
            if (lane >= o) scan += t;
        }
        if (k < NUM_LABELS) {
            cursor[k] = (scan - tot) + mybase;
            if (c == 0) g_counts[k] = tot;
        }
    }
    __syncthreads();

    // Scatter my eighth from registers (warp-aggregated smem cursors)
    #pragma unroll
    for (int s = 0; s < 2; s++) {
        const int4 v = s ? s1 : s0;
        const int b0 = (my_i4 + s) * 4;
        #pragma unroll
        for (int j = 0; j < 4; j++) {
            int lab = (j == 0) ? v.x : (j == 1) ? v.y : (j == 2) ? v.z : v.w;
            unsigned mask = __match_any_sync(0xffffffffu, lab);
            int leader = __ffs(mask) - 1;
            int rank   = __popc(mask & ((1u << lane) - 1u));
            int base = 0;
            if (lane == leader) base = atomicAdd(&cursor[lab], __popc(mask));
            base = __shfl_sync(0xffffffffu, base, leader);
            g_rl[base + rank] = ((b0 + j) << 4) | lab;
        }
    }

    __threadfence();                 // release g_rl / g_counts / out
    __syncthreads();
    if (tid == 0) {
        if (atomicAdd(&g_c1, 1) == PREP_CTAS - 1) {
            g_c1 = 0;
            g_f1 = 1;                // open accum phase
        }
    }
}

// ---------------------------------------------------------------------------
// Phase 3 (noinline): finalize 128 cells for CTA b2 (0..399).
// sse(k,j) = q - 2*m'*s + n*m'^2, m' = s/n - EPS. Zero-restores cells.
// ---------------------------------------------------------------------------
__device__ __noinline__ void finalize_phase(int b2, float* __restrict__ out) {
    __shared__ float sh[4];
    const int tid  = threadIdx.x;
    const int lane = tid & 31;
    const int k = b2 / (FIN_CTAS / NUM_LABELS);          // 40 CTAs per label
    const int j = (b2 % (FIN_CTAS / NUM_LABELS)) * TPB + tid;

    const int idx = k * CH + j;
    float n = (float)g_counts[k];
    float s = g_sum[idx];
    float q = g_sum2[idx];
    g_sum[idx]  = 0.0f;              // restore all-zero invariant
    g_sum2[idx] = 0.0f;

    float acc = 0.0f;
    if (n > 0.0f) {
        float mp = s / n - EPS;
        float e  = q - 2.0f * mp * s + n * mp * mp;
        acc = e / (n * (float)CH);
    }
    #pragma unroll
    for (int o = 16; o > 0; o >>= 1)
        acc += __shfl_down_sync(0xffffffffu, acc, o);
    if (lane == 0) sh[tid >> 5] = acc;
    __syncthreads();
    if (tid == 0) atomicAdd(out, sh[0] + sh[1] + sh[2] + sh[3]);
}

__device__ __forceinline__ void flush_acc(int lab, int colBase,
                                          float4& a, float4& a2) {
    int base = lab * CH + colBase;
    atomicAdd(&g_sum [base + 0], a.x);
    atomicAdd(&g_sum [base + 1], a.y);
    atomicAdd(&g_sum [base + 2], a.z);
    atomicAdd(&g_sum [base + 3], a.w);
    atomicAdd(&g_sum2[base + 0], a2.x);
    atomicAdd(&g_sum2[base + 1], a2.y);
    atomicAdd(&g_sum2[base + 2], a2.z);
    atomicAdd(&g_sum2[base + 3], a2.w);
    a  = make_float4(0.f, 0.f, 0.f, 0.f);
    a2 = make_float4(0.f, 0.f, 0.f, 0.f);
}

// ---------------------------------------------------------------------------
// Megakernel: 648 CTAs, all co-resident (reg cap ~102, 5+ CTAs/SM).
// bids 0..7 prep; bids 8..647 accum, then the first 400 of them finalize.
// ---------------------------------------------------------------------------
__global__ __launch_bounds__(TPB, MIN_CTAS_PER_SM)
void mega_kernel(const float* __restrict__ z,
                 const int* __restrict__ labels,
                 float* __restrict__ out) {
    const int tid = threadIdx.x;
    const int bid = blockIdx.x;

    if (bid < PREP_CTAS) {
        prep_phase(bid, labels, out);
        return;
    }

    // ===================== accum (bids 8..647) ==============================
    __shared__ int s_rl[ROWS_PER_CHUNK];
    const int b  = bid - PREP_CTAS;
    const int cb = b % COL_BLOCKS;   // column block 0..9
    const int rc = b / COL_BLOCKS;   // row chunk   0..63

    if (tid == 0) { while (g_f1 == 0) __nanosleep(256); }
    __syncthreads();
    __threadfence();                 // acquire prep's writes

    s_rl[tid] = g_rl[rc * ROWS_PER_CHUNK + tid];
    __syncthreads();

    const float4* __restrict__ z4 = (const float4*)z;
    const int col4    = cb * (COLS_PER_CTA / 4) + tid;
    const int colBase = cb * COLS_PER_CTA + tid * 4;

    float4 a  = make_float4(0.f, 0.f, 0.f, 0.f);
    float4 a2 = make_float4(0.f, 0.f, 0.f, 0.f);
    int cur = s_rl[0] & 15;

    for (int i = 0; i < ROWS_PER_CHUNK; i += 8) {
        int    rl[8];
        float4 v[8];
        #pragma unroll
        for (int u = 0; u < 8; u++) rl[u] = s_rl[i + u];
        #pragma unroll
        for (int u = 0; u < 8; u++) v[u] = z4[(rl[u] >> 4) * (CH / 4) + col4];

        #pragma unroll
        for (int u = 0; u < 8; u++) {
            int lab = rl[u] & 15;
            if (lab != cur) { flush_acc(cur, colBase, a, a2); cur = lab; }
            a.x += v[u].x; a.y += v[u].y; a.z += v[u].z; a.w += v[u].w;
            a2.x = fmaf(v[u].x, v[u].x, a2.x);
            a2.y = fmaf(v[u].y, v[u].y, a2.y);
            a2.z = fmaf(v[u].z, v[u].z, a2.z);
            a2.w = fmaf(v[u].w, v[u].w, a2.w);
        }
    }
    flush_acc(cur, colBase, a, a2);

    // ---- phase barrier: all accum atomics visible, then finalize ----
    __threadfence();
    __syncthreads();
    if (tid == 0) {
        if (atomicAdd(&g_c2, 1) == ACCUM_CTAS - 1) {
            g_c2 = 0;
            __threadfence();
            g_f2 = 1;                // open finalize phase
        }
        while (g_f2 == 0) __nanosleep(256);   // short: only finish-spread wait
    }
    __syncthreads();
    __threadfence();                 // acquire all CTAs' atomics

    if (b < FIN_CTAS) finalize_phase(b, out);

    __syncthreads();
    if (tid == 0) {
        if (atomicAdd(&g_p2, 1) == ACCUM_CTAS - 1) {
            g_p2 = 0;                // everyone is past the flag spins
            g_f1 = 0;                // reset for next replay
            g_f2 = 0;
        }
    }
}

// ---------------------------------------------------------------------------
extern "C" void kernel_launch(void* const* d_in, const int* in_sizes, int n_in,
                              void* d_out, int out_size) {
    const float* z      = (const float*)d_in[0];
    const int*   labels = (const int*)d_in[1];
    (void)in_sizes; (void)n_in; (void)out_size;

    mega_kernel<<<GRID_CTAS, TPB>>>(z, labels, (float*)d_out);
}